// round 17
// baseline (speedup 1.0000x reference)
#include <cuda_runtime.h>
#include <cstdint>

#define NB      8
#define NHEADS  12
#define HH      24
#define SEQ     576
#define DIM     64
#define NPOS    24
#define BATCH   96
#define KPAD    28          // row stride (words): 16B-aligned; frag reads conflict-free

// Scratch: pe_x_flat / pe_y_flat  [BATCH][SEQ][NPOS]
__device__ __align__(16) float g_Vx[BATCH * SEQ * NPOS];
__device__ __align__(16) float g_Vy[BATCH * SEQ * NPOS];

__device__ __forceinline__ float sigmoidf_(float x) {
    return 1.0f / (1.0f + __expf(-x));
}

__device__ __forceinline__ unsigned long long fma2(unsigned long long a,
                                                   unsigned long long b,
                                                   unsigned long long c) {
    unsigned long long d;
    asm("fma.rn.f32x2 %0, %1, %2, %3;" : "=l"(d) : "l"(a), "l"(b), "l"(c));
    return d;
}

__device__ __forceinline__ unsigned long long pack2(float lo, float hi) {
    unsigned long long r;
    asm("mov.b64 %0, {%1, %2};" : "=l"(r) : "f"(lo), "f"(hi));
    return r;
}

__device__ __forceinline__ float fsqrt_approx(float x) {
    float r;
    asm("sqrt.approx.f32 %0, %1;" : "=f"(r) : "f"(x));
    return r;
}

__device__ __forceinline__ uint32_t f2tf32(float v) {
    uint32_t r;
    asm("cvt.rna.tf32.f32 %0, %1;" : "=r"(r) : "f"(v));
    return r;
}

__device__ __forceinline__ void mma_tf32(float* c, const uint32_t* a, uint32_t b0, uint32_t b1) {
    asm volatile(
        "mma.sync.aligned.m16n8k8.row.col.f32.tf32.tf32.f32 "
        "{%0,%1,%2,%3}, {%4,%5,%6,%7}, {%8,%9}, {%0,%1,%2,%3};"
        : "+f"(c[0]), "+f"(c[1]), "+f"(c[2]), "+f"(c[3])
        : "r"(a[0]), "r"(a[1]), "r"(a[2]), "r"(a[3]), "r"(b0), "r"(b1));
}

// ---------------------------------------------------------------------------
// Kernel 1: fused CoPE (EXACT R12/R16 form — measured ~47.5 us).
// ---------------------------------------------------------------------------
__global__ void __launch_bounds__(512) cope_kernel(
    const float* __restrict__ query,      // [8,12,576,64]
    const float* __restrict__ attn,       // [8,12,576,576]
    const float* __restrict__ pex,        // [64,24]
    const float* __restrict__ pey)        // [64,24]
{
    __shared__ __align__(16) float q_s[2][HH * 68];
    __shared__ __align__(16) float pe_s[2][DIM * NPOS];
    __shared__ __align__(8)  float li[2][HH * 26];

    int t    = threadIdx.x;
    int path = t >> 8;
    int tp   = t & 255;

    int id   = blockIdx.x;
    int n    = id / 12;
    int m    = id % 12;
    int b_a  = id / 288;
    int hd_a = (id / 24) % 12;
    int r_a  = id % 24;
    int b_q  = n / 24;
    int s_q  = n % 24;

    {
        const float4* pe4 = (const float4*)(path ? pey : pex);
        float4* d4 = (float4*)pe_s[path];
        for (int idx = tp; idx < DIM * NPOS / 4; idx += 256)
            d4[idx] = pe4[idx];
    }

    if (!path) {
        const float4* qb = (const float4*)(query + (((size_t)(b_q * 12 + m)) * SEQ + s_q * 24) * DIM);
        for (int idx = tp; idx < HH * DIM / 4; idx += 256) {
            int rr = idx >> 4, c4 = (idx & 15) * 4;
            *(float4*)&q_s[0][rr * 68 + c4] = qb[idx];
        }
    } else {
        const float* qb = query + (((size_t)(b_q * 12 + m)) * SEQ + s_q) * DIM;
        for (int idx = tp; idx < HH * DIM / 4; idx += 256) {
            int rr = idx >> 4, c4 = (idx & 15) * 4;
            *(float4*)&q_s[1][rr * 68 + c4] = *(const float4*)(qb + (size_t)rr * (24 * DIM) + c4);
        }
    }
    __syncthreads();

    for (int o = t; o < 2 * HH * 12; o += 512) {
        int pa  = (o >= 288) ? 1 : 0;
        int rem = o - pa * 288;
        int j   = rem / 12;
        int pp  = rem - j * 12;
        const float4* qr4 = (const float4*)&q_s[pa][j * 68];
        const float*  pr  = pe_s[pa] + 2 * pp;
        unsigned long long acc = 0ull;
        #pragma unroll
        for (int dq = 0; dq < 16; dq++) {
            float4 q4 = qr4[dq];
            float2 v0 = *(const float2*)(pr + (4 * dq + 0) * NPOS);
            float2 v1 = *(const float2*)(pr + (4 * dq + 1) * NPOS);
            float2 v2 = *(const float2*)(pr + (4 * dq + 2) * NPOS);
            float2 v3 = *(const float2*)(pr + (4 * dq + 3) * NPOS);
            acc = fma2(pack2(q4.x, q4.x), pack2(v0.x, v0.y), acc);
            acc = fma2(pack2(q4.y, q4.y), pack2(v1.x, v1.y), acc);
            acc = fma2(pack2(q4.z, q4.z), pack2(v2.x, v2.y), acc);
            acc = fma2(pack2(q4.w, q4.w), pack2(v3.x, v3.y), acc);
        }
        *(float2*)(&li[pa][j * 26 + 2 * pp]) = *(float2*)&acc;
    }
    __syncthreads();

    int w    = (t >> 5) & 7;
    int lane = t & 31;
    int bh   = b_q * 12 + m;
    for (int j = w; j < HH; j += 8) {
        const float* arow;
        int astride;
        float* dst;
        if (!path) {
            arow = attn + (((size_t)(b_a * 12 + hd_a)) * SEQ + (size_t)(r_a * 24 + j)) * SEQ
                        + (size_t)(r_a * 24);
            astride = 1;
            dst = g_Vx + ((size_t)bh * SEQ + (size_t)(s_q * 24 + j)) * NPOS;
        } else {
            arow = attn + (((size_t)(b_a * 12 + hd_a)) * SEQ + (size_t)(j * 24 + r_a)) * SEQ
                        + (size_t)r_a;
            astride = 24;
            dst = g_Vy + ((size_t)bh * SEQ + (size_t)(j * 24 + s_q)) * NPOS;
        }
        float v = 0.0f;
        if (lane < NPOS)
            v = sigmoidf_(arow[lane * astride]);
        #pragma unroll
        for (int d = 1; d < 32; d <<= 1) {
            float tv = __shfl_down_sync(0xffffffffu, v, d);
            if (lane + d < NPOS) v += tv;
        }
        if (lane < NPOS) {
            float pp = fminf(v, (float)(NPOS - 1));
            float pf = floorf(pp);
            int   ifl = (int)pf;
            int   ic  = (int)ceilf(pp);
            float wq  = pp - pf;
            float val = li[path][j * 26 + ic] * wq + li[path][j * 26 + ifl] * (1.0f - wq);
            dst[lane] = val;
        }
    }
}

// ---------------------------------------------------------------------------
// Kernel 2: fused double-cdist + mix via tf32 mma, PATH-PARALLEL warp groups.
// Block 256 = 8 warps: warps 0-3 = x-path, warps 4-7 = y-path (concurrent).
// Warp wg owns rows 16wg..16wg+15 of its path's 64x64 Gram.
// y-group deposits scaled distances to xch; one barrier; x-group combines,
// diag-zeroes (diagonal tiles only), writes back; all 256 threads stream out.
// ---------------------------------------------------------------------------
__global__ void __launch_bounds__(256) dist_kernel(
    const float* __restrict__ wxp,
    float* __restrict__ out)
{
    __shared__ __align__(16) float sV[2][2][64 * KPAD];   // [path][A/B][row][k]
    __shared__ float xch[64 * 65];
    __shared__ float nrm[2][2][64];

    int bz = blockIdx.y;
    int u = blockIdx.x;
    int ti = 0;
    #pragma unroll 1
    while (u >= (9 - ti)) { u -= (9 - ti); ti++; }
    int tj = ti + u;
    int p0 = ti * 64;
    int q0 = tj * 64;

    int t    = threadIdx.x;     // 0..255
    int w    = t >> 5;
    int lane = t & 31;
    int pa   = w >> 2;          // warp group = path
    int wg   = w & 3;           // m-strip within group

    // ---- Load + cvt + partner-shfl norm ----
    // threads 0-127 handle path 0 (groups ab=0,1); 128-255 handle path 1.
    {
        int rr  = (t >> 1) & 63;
        int hf  = t & 1;
        int pl  = t >> 7;       // path to load
        const float* V = pl ? g_Vy : g_Vx;
        #pragma unroll
        for (int ab = 0; ab < 2; ab++) {
            const float* src = V + ((size_t)bz * SEQ + (ab ? q0 : p0) + rr) * NPOS + hf * 4;
            float* dstrow = &sV[pl][ab][rr * KPAD + hf * 4];
            float np = 0.0f;
            #pragma unroll
            for (int i = 0; i < 3; i++) {
                float4 v4 = *(const float4*)(src + 8 * i);
                float4 tv;
                tv.x = __uint_as_float(f2tf32(v4.x));
                tv.y = __uint_as_float(f2tf32(v4.y));
                tv.z = __uint_as_float(f2tf32(v4.z));
                tv.w = __uint_as_float(f2tf32(v4.w));
                *(float4*)(dstrow + 8 * i) = tv;
                np = fmaf(tv.x, tv.x, np);
                np = fmaf(tv.y, tv.y, np);
                np = fmaf(tv.z, tv.z, np);
                np = fmaf(tv.w, tv.w, np);
            }
            np += __shfl_xor_sync(0xffffffffu, np, 1);
            if (!hf) nrm[pl][ab][rr] = np;
        }
    }
    __syncthreads();

    float wxv = *wxp;
    int rl = lane >> 2;          // 0..7
    int cg = lane & 3;           // 0..3
    int rowA = 16 * wg + rl;

    // ---- Mainloop: ONE path per warp group ----
    const float* arow0 = sV[pa][0] + rowA * KPAD + cg;
    const float* arow1 = arow0 + 8 * KPAD;
    const float* bbase = sV[pa][1] + rl * KPAD + cg;

    float acc[8][4];
    #pragma unroll
    for (int nt = 0; nt < 8; nt++)
        #pragma unroll
        for (int e = 0; e < 4; e++) acc[nt][e] = 0.0f;

    #pragma unroll
    for (int ks = 0; ks < 3; ks++) {
        uint32_t a[4];
        a[0] = __float_as_uint(arow0[8 * ks]);
        a[1] = __float_as_uint(arow1[8 * ks]);
        a[2] = __float_as_uint(arow0[8 * ks + 4]);
        a[3] = __float_as_uint(arow1[8 * ks + 4]);
        #pragma unroll
        for (int nt = 0; nt < 8; nt++) {
            uint32_t b0 = __float_as_uint(bbase[nt * 8 * KPAD + 8 * ks]);
            uint32_t b1 = __float_as_uint(bbase[nt * 8 * KPAD + 8 * ks + 4]);
            mma_tf32(acc[nt], a, b0, b1);
        }
    }

    // ---- Distances for own path (in place) ----
    {
        float scale = pa ? (1.0f - wxv) : wxv;
        float na0 = nrm[pa][0][rowA];
        float na1 = nrm[pa][0][rowA + 8];
        #pragma unroll
        for (int nt = 0; nt < 8; nt++) {
            int c = 8 * nt + 2 * cg;
            float nb0 = nrm[pa][1][c], nb1 = nrm[pa][1][c + 1];
            acc[nt][0] = scale * fsqrt_approx(fmaxf(fmaf(-2.0f, acc[nt][0], na0 + nb0), 0.0f));
            acc[nt][1] = scale * fsqrt_approx(fmaxf(fmaf(-2.0f, acc[nt][1], na0 + nb1), 0.0f));
            acc[nt][2] = scale * fsqrt_approx(fmaxf(fmaf(-2.0f, acc[nt][2], na1 + nb0), 0.0f));
            acc[nt][3] = scale * fsqrt_approx(fmaxf(fmaf(-2.0f, acc[nt][3], na1 + nb1), 0.0f));
        }
    }

    // ---- y-group deposits, x-group combines ----
    if (pa == 1) {
        #pragma unroll
        for (int nt = 0; nt < 8; nt++) {
            int c = 8 * nt + 2 * cg;
            xch[rowA * 65 + c]           = acc[nt][0];
            xch[rowA * 65 + c + 1]       = acc[nt][1];
            xch[(rowA + 8) * 65 + c]     = acc[nt][2];
            xch[(rowA + 8) * 65 + c + 1] = acc[nt][3];
        }
    }
    __syncthreads();
    if (pa == 0) {
        #pragma unroll
        for (int nt = 0; nt < 8; nt++) {
            int c = 8 * nt + 2 * cg;
            float f0 = acc[nt][0] + xch[rowA * 65 + c];
            float f1 = acc[nt][1] + xch[rowA * 65 + c + 1];
            float f2v = acc[nt][2] + xch[(rowA + 8) * 65 + c];
            float f3 = acc[nt][3] + xch[(rowA + 8) * 65 + c + 1];
            if (ti == tj) {
                if (rowA     == c)     f0 = 0.0f;
                if (rowA     == c + 1) f1 = 0.0f;
                if (rowA + 8 == c)     f2v = 0.0f;
                if (rowA + 8 == c + 1) f3 = 0.0f;
            }
            xch[rowA * 65 + c]           = f0;
            xch[rowA * 65 + c + 1]       = f1;
            xch[(rowA + 8) * 65 + c]     = f2v;
            xch[(rowA + 8) * 65 + c + 1] = f3;
        }
    }
    __syncthreads();

    // ---- Primary tile: coalesced float4 writes (all 256 threads) ----
    for (int idx = t; idx < 1024; idx += 256) {
        int r = idx >> 4, c = (idx & 15) * 4;
        const float* xr = &xch[r * 65 + c];
        float4 v = make_float4(xr[0], xr[1], xr[2], xr[3]);
        *(float4*)(out + ((size_t)bz * SEQ + (p0 + r)) * SEQ + q0 + c) = v;
    }

    // ---- Mirror tile for off-diagonal pairs ----
    if (ti != tj) {
        for (int idx = t; idx < 1024; idx += 256) {
            int r = idx >> 4, c = (idx & 15) * 4;
            float4 v = make_float4(xch[(c + 0) * 65 + r],
                                   xch[(c + 1) * 65 + r],
                                   xch[(c + 2) * 65 + r],
                                   xch[(c + 3) * 65 + r]);
            *(float4*)(out + ((size_t)bz * SEQ + (q0 + r)) * SEQ + p0 + c) = v;
        }
    }
}

// ---------------------------------------------------------------------------
extern "C" void kernel_launch(void* const* d_in, const int* in_sizes, int n_in,
                              void* d_out, int out_size) {
    const float* query = (const float*)d_in[0];
    const float* attn  = (const float*)d_in[1];
    const float* pex   = (const float*)d_in[2];
    const float* pey   = (const float*)d_in[3];
    const float* wx    = (const float*)d_in[4];
    float* out = (float*)d_out;

    cope_kernel<<<2304, 512>>>(query, attn, pex, pey);

    dim3 dgrid(45, BATCH);
    dist_kernel<<<dgrid, 256>>>(wx, out);
}